// round 2
// baseline (speedup 1.0000x reference)
#include <cuda_runtime.h>
#include <cstdint>

#define BATCH 512
#define TLEN  1024
#define NST   64

// Packed f32x2 helpers (Blackwell FFMA2 path — only reachable via PTX f32x2)
#define FMA2(d, a, b, c) asm("fma.rn.f32x2 %0, %1, %2, %3;" : "=l"(d) : "l"(a), "l"(b), "l"(c))
#define ADD2(d, a, b)    asm("add.rn.f32x2 %0, %1, %2;"     : "=l"(d) : "l"(a), "l"(b))
#define UNPACK2(lo, hi, s) asm("mov.b64 {%0, %1}, %2;"      : "=f"(lo), "=f"(hi) : "l"(s))

__device__ __forceinline__ float fexp(float x) {
    float y;
    asm("ex2.approx.f32 %0, %1;" : "=f"(y) : "f"(x * 1.4426950408889634f));
    return y;
}
__device__ __forceinline__ float ex2f(float x) {
    float y;
    asm("ex2.approx.f32 %0, %1;" : "=f"(y) : "f"(x));
    return y;
}
__device__ __forceinline__ float flog(float x) {
    float y;
    asm("lg2.approx.f32 %0, %1;" : "=f"(y) : "f"(x));
    return y * 0.6931471805599453f;
}

// g_E[i*64 + j] = exp(transitions[i][j])  (natural row-major; column pairs are adjacent)
__device__ float g_E[NST * NST];

__global__ void prep_kernel(const float* __restrict__ trans) {
    for (int k = threadIdx.x; k < NST * NST; k += blockDim.x)
        g_E[k] = expf(trans[k]);
}

// One CTA (64 threads = 2 warps) per chain.
// Warp W owns columns [32W, 32W+32) as 16 packed pairs; lane = (h<<4)|p:
//   col pair p -> columns (32W+2p, 32W+2p+1); half h -> i in [32h, 32h+32).
// Each thread: 32 FFMA2 over its i-half, then shfl_xor(16) combine.
__global__ void __launch_bounds__(64) crf_kernel(
    const float* __restrict__ unary,
    const int*   __restrict__ lengths,
    float*       __restrict__ out)
{
    const int tid  = threadIdx.x;
    const int W    = tid >> 5;
    const int lane = tid & 31;
    const int p    = lane & 15;
    const int h    = lane >> 4;
    const int b    = blockIdx.x;
    const int c    = 32 * W + 2 * p + h;   // this thread's published column

    // E slice in registers: cE[k] = (E[i][c0], E[i][c0+1]) for i = 32h+k, c0 = 32W+2p
    unsigned long long cE[32];
    const unsigned long long* E2 = (const unsigned long long*)g_E;
    #pragma unroll
    for (int k = 0; k < 32; k++)
        cE[k] = E2[(32 * h + k) * 32 + 16 * W + p];

    // double-buffered duplicated broadcast: wdup[buf][j] = (w_j, w_j)
    __shared__ __align__(16) float2 wdup[2][NST];
    __shared__ float wmax[2];
    __shared__ float ssum[2];

    int len = lengths[b];
    if (len < 1) len = 1;
    const float* ub = unary + (size_t)b * (TLEN * NST);

    // w0 = exp(u0) for my column
    float w = fexp(ub[c]);
    wdup[0][c] = make_float2(w, w);

    int   ktot = 0;       // accumulated power-of-2 scale (exact integer)
    // register prefetch of this thread's unary column, distance 2
    float u1 = 0.f, u2 = 0.f;
    if (len > 1) u1 = ub[NST + c];
    if (len > 2) u2 = ub[2 * NST + c]; else u2 = u1;

    const float L2E = 1.4426950408889634f;
    int buf = 0;

    for (int t = 1; t < len; t++) {
        __syncthreads();

        // lagged renorm apply: max published at t-2 (t-2 ≡ 0 mod 4), applied here.
        float kf = 0.0f;
        if ((t & 3) == 2 && t > 4) {
            float m = fmaxf(wmax[0], wmax[1]);
            int e = ((__float_as_int(m) >> 23) & 255) - 127;
            ktot += e;
            kf = (float)e;
        }
        // eu = exp(u_t) * 2^-k  folded into one MUFU
        float eu = ex2f(fmaf(u1, L2E, -kf));

        // matvec partial over my i-half: 32 FFMA2
        const ulonglong2* P = (const ulonglong2*)(&wdup[buf][32 * h]);
        unsigned long long a0 = 0ull, a1 = 0ull, a2 = 0ull, a3 = 0ull;
        #pragma unroll
        for (int k = 0; k < 32; k += 4) {
            ulonglong2 x = P[(k >> 1) + 0];
            ulonglong2 y = P[(k >> 1) + 1];
            FMA2(a0, x.x, cE[k + 0], a0);
            FMA2(a1, x.y, cE[k + 1], a1);
            FMA2(a2, y.x, cE[k + 2], a2);
            FMA2(a3, y.y, cE[k + 3], a3);
        }
        ADD2(a0, a0, a1);
        ADD2(a2, a2, a3);
        ADD2(a0, a0, a2);

        // combine the two i-halves: lanes l and l^16 hold complementary partials
        unsigned long long o =
            (unsigned long long)__shfl_xor_sync(0xffffffffu, (long long)a0, 16);
        ADD2(a0, a0, o);

        float qx, qy;
        UNPACK2(qx, qy, a0);
        float q = h ? qy : qx;   // my column's element of the pair
        w = q * eu;

        // prefetch next unary values (distance 2 in regs, distance 8 to L2)
        u1 = u2;
        int tn = (t + 2 < len) ? t + 2 : len - 1;
        u2 = ub[(size_t)tn * NST + c];
        {
            int tp = (t + 8 < len) ? t + 8 : len - 1;
            asm volatile("prefetch.global.L2 [%0];" :: "l"(ub + (size_t)tp * NST + c));
        }

        // renorm publish every 4 steps (butterfly overlaps next step's work via lag)
        if ((t & 3) == 0) {
            float m = w;
            #pragma unroll
            for (int off = 16; off; off >>= 1)
                m = fmaxf(m, __shfl_xor_sync(0xffffffffu, m, off));
            if (lane == 0) wmax[W] = m;
        }

        wdup[buf ^ 1][c] = make_float2(w, w);
        buf ^= 1;
    }

    // out[b] = ktot*ln2 + log(sum_j w_j)
    float s = w;
    #pragma unroll
    for (int off = 16; off; off >>= 1)
        s += __shfl_xor_sync(0xffffffffu, s, off);
    if (lane == 0) ssum[W] = s;
    __syncthreads();
    if (tid == 0)
        out[b] = (float)ktot * 0.6931471805599453f + flog(ssum[0] + ssum[1]);
}

extern "C" void kernel_launch(void* const* d_in, const int* in_sizes, int n_in,
                              void* d_out, int out_size) {
    const float* unary   = nullptr;
    const int*   lengths = nullptr;
    const float* trans   = nullptr;
    for (int i = 0; i < n_in; i++) {
        if (in_sizes[i] == BATCH * TLEN * NST) unary   = (const float*)d_in[i];
        else if (in_sizes[i] == BATCH)         lengths = (const int*)d_in[i];
        else if (in_sizes[i] == NST * NST)     trans   = (const float*)d_in[i];
    }
    prep_kernel<<<1, 256>>>(trans);
    crf_kernel<<<BATCH, 64>>>(unary, lengths, (float*)d_out);
}

// round 3
// speedup vs baseline: 1.2198x; 1.2198x over previous
#include <cuda_runtime.h>
#include <cstdint>

#define BATCH 512
#define TLEN  1024
#define NST   64

typedef unsigned long long ull;

// Packed f32x2 helpers (Blackwell FFMA2 path — only reachable via PTX f32x2)
#define FMA2(d, a, b, c) asm("fma.rn.f32x2 %0, %1, %2, %3;" : "=l"(d) : "l"(a), "l"(b), "l"(c))
#define ADD2(d, a, b)    asm("add.rn.f32x2 %0, %1, %2;"     : "=l"(d) : "l"(a), "l"(b))
#define UNPACK2(lo, hi, s) asm("mov.b64 {%0, %1}, %2;"      : "=f"(lo), "=f"(hi) : "l"(s))

__device__ __forceinline__ float fexp(float x) {
    float y;
    asm("ex2.approx.f32 %0, %1;" : "=f"(y) : "f"(x * 1.4426950408889634f));
    return y;
}
__device__ __forceinline__ float ex2f(float x) {
    float y;
    asm("ex2.approx.f32 %0, %1;" : "=f"(y) : "f"(x));
    return y;
}
__device__ __forceinline__ float flog(float x) {
    float y;
    asm("lg2.approx.f32 %0, %1;" : "=f"(y) : "f"(x));
    return y * 0.6931471805599453f;
}

// Transposed i-pair packing:
// g_Ep[c][k] = ( exp(trans[2k][c]), exp(trans[2k+1][c]) ),  c in [0,64), k in [0,32)
__device__ __align__(16) float2 g_Ep[NST][NST / 2];

__global__ void prep_kernel(const float* __restrict__ trans) {
    for (int idx = threadIdx.x; idx < NST * (NST / 2); idx += blockDim.x) {
        int c = idx >> 5, k = idx & 31;
        g_Ep[c][k] = make_float2(expf(trans[(2 * k) * NST + c]),
                                 expf(trans[(2 * k + 1) * NST + c]));
    }
}

// One warp per chain; 4 warps per CTA; 128 CTAs (<=1 CTA per SM => 1 warp per SMSP).
// Thread l owns adjacent columns (2l, 2l+1).
// f32x2 packs along i: accumulator lanes hold even-i / odd-i partial sums.
__global__ void __launch_bounds__(128, 1) crf_kernel(
    const float* __restrict__ unary,
    const int*   __restrict__ lengths,
    float*       __restrict__ out)
{
    const int tid  = threadIdx.x;
    const int wid  = tid >> 5;
    const int l    = tid & 31;
    const int b    = (blockIdx.x << 2) + wid;
    const int c0   = 2 * l;

    // E slices in registers: 64 packed pairs (128 regs)
    ull cE0[32], cE1[32];
    const ull* Ep = (const ull*)g_Ep;
    #pragma unroll
    for (int k = 0; k < 32; k++) {
        cE0[k] = Ep[c0 * 32 + k];
        cE1[k] = Ep[(c0 + 1) * 32 + k];
    }

    // unduplicated w broadcast, double-buffered, per warp (256B each)
    __shared__ __align__(16) float wbuf[4][2][NST];
    __shared__ int sexp[4];

    int len = lengths[b];
    if (len < 1) len = 1;
    const float* ub = unary + (size_t)b * (TLEN * NST);

    // w0 = exp(u0)
    float2 u0v = *(const float2*)(ub + c0);
    float w0 = fexp(u0v.x);
    float w1 = fexp(u0v.y);
    *(float2*)&wbuf[wid][0][c0] = make_float2(w0, w1);

    int ktot = 0;
    // register prefetch of this thread's two unary values, distance 2
    float uA0 = 0.f, uA1 = 0.f, uB0 = 0.f, uB1 = 0.f;
    if (len > 1) { float2 v = *(const float2*)(ub + NST + c0);     uA0 = v.x; uA1 = v.y; }
    if (len > 2) { float2 v = *(const float2*)(ub + 2 * NST + c0); uB0 = v.x; uB1 = v.y; }
    else         { uB0 = uA0; uB1 = uA1; }

    const float L2E = 1.4426950408889634f;
    int buf = 0;

    for (int t = 1; t < len; t++) {
        __syncwarp();

        // lagged renorm apply (published 2 steps ago), folded into the MUFU arg
        float kf = 0.0f;
        if ((t & 3) == 2 && t >= 6) {
            int e = sexp[wid];
            ktot += e;
            kf = (float)e;
        }
        // hoisted before FFMA stream so MUFU latency hides under it
        float eu0 = ex2f(fmaf(uA0, L2E, -kf));
        float eu1 = ex2f(fmaf(uA1, L2E, -kf));

        // matvec: 16 broadcast LDS.128 + 64 FFMA2 (pair lanes = even-i / odd-i sums)
        const ulonglong2* P = (const ulonglong2*)wbuf[wid][buf];
        ull a00 = 0ull, a01 = 0ull, a10 = 0ull, a11 = 0ull;
        #pragma unroll
        for (int m = 0; m < 16; m++) {
            ulonglong2 x = P[m];
            FMA2(a00, x.x, cE0[2 * m],     a00);
            FMA2(a01, x.y, cE0[2 * m + 1], a01);
            FMA2(a10, x.x, cE1[2 * m],     a10);
            FMA2(a11, x.y, cE1[2 * m + 1], a11);
        }
        ADD2(a00, a00, a01);
        ADD2(a10, a10, a11);
        float s0lo, s0hi, s1lo, s1hi;
        UNPACK2(s0lo, s0hi, a00);
        UNPACK2(s1lo, s1hi, a10);
        w0 = (s0lo + s0hi) * eu0;
        w1 = (s1lo + s1hi) * eu1;

        // shift unary prefetch window
        uA0 = uB0; uA1 = uB1;
        int tn = (t + 2 < len) ? t + 2 : len - 1;
        float2 v = *(const float2*)(ub + (size_t)tn * NST + c0);
        uB0 = v.x; uB1 = v.y;

        // renorm publish: lane 0's exponent (exact power of 2), applied at t+2
        if ((t & 3) == 0 && l == 0) {
            int e = ((__float_as_int(w0) >> 23) & 255) - 127;
            e = e < -100 ? -100 : (e > 100 ? 100 : e);
            sexp[wid] = e;
        }

        *(float2*)&wbuf[wid][buf ^ 1][c0] = make_float2(w0, w1);
        buf ^= 1;
    }

    // out[b] = ktot*ln2 + log(sum_j w_j)
    float s = w0 + w1;
    #pragma unroll
    for (int off = 16; off; off >>= 1)
        s += __shfl_xor_sync(0xffffffffu, s, off);
    if (l == 0)
        out[b] = (float)ktot * 0.6931471805599453f + flog(s);
}

extern "C" void kernel_launch(void* const* d_in, const int* in_sizes, int n_in,
                              void* d_out, int out_size) {
    const float* unary   = nullptr;
    const int*   lengths = nullptr;
    const float* trans   = nullptr;
    for (int i = 0; i < n_in; i++) {
        if (in_sizes[i] == BATCH * TLEN * NST) unary   = (const float*)d_in[i];
        else if (in_sizes[i] == BATCH)         lengths = (const int*)d_in[i];
        else if (in_sizes[i] == NST * NST)     trans   = (const float*)d_in[i];
    }
    prep_kernel<<<1, 256>>>(trans);
    crf_kernel<<<BATCH / 4, 128>>>(unary, lengths, (float*)d_out);
}

// round 4
// speedup vs baseline: 1.3272x; 1.0880x over previous
#include <cuda_runtime.h>
#include <cstdint>

#define BATCH 512
#define TLEN  1024
#define NST   64

typedef unsigned long long ull;

// Packed f32x2 helpers (Blackwell FFMA2 path — only reachable via PTX f32x2)
#define FMA2(d, a, b, c) asm("fma.rn.f32x2 %0, %1, %2, %3;" : "=l"(d) : "l"(a), "l"(b), "l"(c))
#define ADD2(d, a, b)    asm("add.rn.f32x2 %0, %1, %2;"     : "=l"(d) : "l"(a), "l"(b))
#define UNPACK2(lo, hi, s) asm("mov.b64 {%0, %1}, %2;"      : "=f"(lo), "=f"(hi) : "l"(s))

__device__ __forceinline__ float fexp(float x) {
    float y;
    asm("ex2.approx.f32 %0, %1;" : "=f"(y) : "f"(x * 1.4426950408889634f));
    return y;
}
__device__ __forceinline__ float ex2f(float x) {
    float y;
    asm("ex2.approx.f32 %0, %1;" : "=f"(y) : "f"(x));
    return y;
}
__device__ __forceinline__ float flog(float x) {
    float y;
    asm("lg2.approx.f32 %0, %1;" : "=f"(y) : "f"(x));
    return y * 0.6931471805599453f;
}

// Transposed i-pair packing:
// g_Ep[c][k] = ( exp(trans[2k][c]), exp(trans[2k+1][c]) ),  c in [0,64), k in [0,32)
__device__ __align__(16) float2 g_Ep[NST][NST / 2];

__global__ void prep_kernel(const float* __restrict__ trans) {
    for (int idx = threadIdx.x; idx < NST * (NST / 2); idx += blockDim.x) {
        int c = idx >> 5, k = idx & 31;
        g_Ep[c][k] = make_float2(expf(trans[(2 * k) * NST + c]),
                                 expf(trans[(2 * k + 1) * NST + c]));
    }
}

// One CTA (64 threads = 2 warps) per chain; thread tid owns column c = tid.
// Per step: 32 FFMA2 (i packed in f32x2 pairs), pair lanes folded locally.
// Exchange: STS.32 publish + __syncthreads + 16 broadcast LDS.128.
__global__ void __launch_bounds__(64) crf_kernel(
    const float* __restrict__ unary,
    const int*   __restrict__ lengths,
    float*       __restrict__ out)
{
    const int tid = threadIdx.x;
    const int W   = tid >> 5;
    const int l   = tid & 31;
    const int b   = blockIdx.x;
    const int c   = tid;

    // E column slice in registers: 32 packed i-pairs (64 regs)
    ull cE[32];
    const ull* Ep = (const ull*)g_Ep;
    #pragma unroll
    for (int k = 0; k < 32; k++)
        cE[k] = Ep[c * 32 + k];

    __shared__ __align__(16) float wbuf[2][NST];
    __shared__ int   sexp;
    __shared__ float ssum[2];

    int len = lengths[b];
    if (len < 1) len = 1;
    const float* ub = unary + (size_t)b * (TLEN * NST);

    // w0 = exp(u0) for my column
    float w = fexp(ub[c]);
    wbuf[0][c] = w;

    int ktot = 0;
    // distance-3 register prefetch pipeline of this thread's unary column
    float uA = 0.f, uB = 0.f, uC = 0.f;
    if (len > 1) uA = ub[NST + c];
    if (len > 2) uB = ub[2 * NST + c]; else uB = uA;
    if (len > 3) uC = ub[3 * NST + c]; else uC = uB;

    const float L2E = 1.4426950408889634f;
    int buf = 0;

    for (int t = 1; t < len; t++) {
        __syncthreads();

        // lagged renorm apply (published at t-2), folded into the MUFU arg
        float kf = 0.0f;
        if ((t & 3) == 2 && t >= 6) {
            int e = sexp;
            ktot += e;
            kf = (float)e;
        }
        // hoisted before the FFMA stream so MUFU latency hides under it
        float eu = ex2f(fmaf(uA, L2E, -kf));

        // matvec for my column: 16 broadcast LDS.128 + 32 FFMA2
        const ulonglong2* P = (const ulonglong2*)wbuf[buf];
        ull a0 = 0ull, a1 = 0ull, a2 = 0ull, a3 = 0ull;
        #pragma unroll
        for (int m = 0; m < 16; m += 2) {
            ulonglong2 x = P[m];
            ulonglong2 y = P[m + 1];
            FMA2(a0, x.x, cE[2 * m + 0], a0);
            FMA2(a1, x.y, cE[2 * m + 1], a1);
            FMA2(a2, y.x, cE[2 * m + 2], a2);
            FMA2(a3, y.y, cE[2 * m + 3], a3);
        }
        ADD2(a0, a0, a1);
        ADD2(a2, a2, a3);
        ADD2(a0, a0, a2);
        float slo, shi;
        UNPACK2(slo, shi, a0);
        w = (slo + shi) * eu;

        // shift unary pipeline (distance 3) + far L2 prefetch every 4th step
        uA = uB; uB = uC;
        int tn = (t + 3 < len) ? t + 3 : len - 1;
        uC = ub[(size_t)tn * NST + c];
        if ((t & 3) == 1) {
            int tp = (t + 16 < len) ? t + 16 : len - 1;
            asm volatile("prefetch.global.L2 [%0];" :: "l"(ub + (size_t)tp * NST + c));
        }

        // renorm publish: thread 0's exponent (exact power of 2), applied at t+2
        if ((t & 3) == 0 && tid == 0) {
            int e = ((__float_as_int(w) >> 23) & 255) - 127;
            e = e < -100 ? -100 : (e > 100 ? 100 : e);
            sexp = e;
        }

        wbuf[buf ^ 1][c] = w;
        buf ^= 1;
    }

    // out[b] = ktot*ln2 + log(sum_j w_j)  (warp reduce + cross-warp via smem)
    float s = w;
    #pragma unroll
    for (int off = 16; off; off >>= 1)
        s += __shfl_xor_sync(0xffffffffu, s, off);
    if (l == 0) ssum[W] = s;
    __syncthreads();
    if (tid == 0)
        out[b] = (float)ktot * 0.6931471805599453f + flog(ssum[0] + ssum[1]);
}

extern "C" void kernel_launch(void* const* d_in, const int* in_sizes, int n_in,
                              void* d_out, int out_size) {
    const float* unary   = nullptr;
    const int*   lengths = nullptr;
    const float* trans   = nullptr;
    for (int i = 0; i < n_in; i++) {
        if (in_sizes[i] == BATCH * TLEN * NST) unary   = (const float*)d_in[i];
        else if (in_sizes[i] == BATCH)         lengths = (const int*)d_in[i];
        else if (in_sizes[i] == NST * NST)     trans   = (const float*)d_in[i];
    }
    prep_kernel<<<1, 256>>>(trans);
    crf_kernel<<<BATCH, 64>>>(unary, lengths, (float*)d_out);
}